// round 1
// baseline (speedup 1.0000x reference)
#include <cuda_runtime.h>
#include <cstdint>

// LWTA over groups of 4 consecutive fp32 units. One float4 == one pool group.
// Keep first max (strict > preserves jnp.argmax first-tie semantics), zero rest.

__device__ __forceinline__ float4 lwta4(float4 v) {
    // find first-max index with strict greater-than
    float m = v.x; int idx = 0;
    if (v.y > m) { m = v.y; idx = 1; }
    if (v.z > m) { m = v.z; idx = 2; }
    if (v.w > m) { m = v.w; idx = 3; }
    float4 r;
    r.x = (idx == 0) ? v.x : 0.0f;
    r.y = (idx == 1) ? v.y : 0.0f;
    r.z = (idx == 2) ? v.z : 0.0f;
    r.w = (idx == 3) ? v.w : 0.0f;
    return r;
}

__global__ void __launch_bounds__(256) lwta_kernel(const float4* __restrict__ in,
                                                   float4* __restrict__ out,
                                                   int n_groups) {
    // 2 groups per thread, front-batched loads for MLP
    int base = (blockIdx.x * blockDim.x + threadIdx.x) * 2;
    if (base + 1 < n_groups) {
        float4 a = in[base];
        float4 b = in[base + 1];
        out[base]     = lwta4(a);
        out[base + 1] = lwta4(b);
    } else if (base < n_groups) {
        out[base] = lwta4(in[base]);
    }
}

extern "C" void kernel_launch(void* const* d_in, const int* in_sizes, int n_in,
                              void* d_out, int out_size) {
    const float4* in = (const float4*)d_in[0];
    float4* out = (float4*)d_out;
    int n = in_sizes[0];          // 4096*8192 = 33554432 floats
    int n_groups = n / 4;          // 8388608 float4 groups
    int groups_per_block = 256 * 2;
    int blocks = (n_groups + groups_per_block - 1) / groups_per_block;  // 16384
    lwta_kernel<<<blocks, 256>>>(in, out, n_groups);
}

// round 2
// speedup vs baseline: 1.2329x; 1.2329x over previous
#include <cuda_runtime.h>
#include <cstdint>

// LWTA over groups of 4 consecutive fp32 units. One float4 == one pool group.
// Keep first max (strict > preserves jnp.argmax first-tie semantics), zero rest.
// Block-strided unroll-4: every LDG.128 / STG.128 is fully coalesced
// (warp covers 512B contiguous), front-batched loads for MLP=4.

__device__ __forceinline__ float4 lwta4(float4 v) {
    float m = v.x; int idx = 0;
    if (v.y > m) { m = v.y; idx = 1; }
    if (v.z > m) { m = v.z; idx = 2; }
    if (v.w > m) { m = v.w; idx = 3; }
    float4 r;
    r.x = (idx == 0) ? v.x : 0.0f;
    r.y = (idx == 1) ? v.y : 0.0f;
    r.z = (idx == 2) ? v.z : 0.0f;
    r.w = (idx == 3) ? v.w : 0.0f;
    return r;
}

__global__ void __launch_bounds__(256) lwta_kernel(const float4* __restrict__ in,
                                                   float4* __restrict__ out,
                                                   int n_groups) {
    const int UNROLL = 4;
    int block_base = blockIdx.x * (blockDim.x * UNROLL);
    int tid = block_base + threadIdx.x;

    if (block_base + blockDim.x * UNROLL <= n_groups) {
        // fast path: all 4 in range, front-batch loads
        float4 a = __ldcs(&in[tid]);
        float4 b = __ldcs(&in[tid + 256]);
        float4 c = __ldcs(&in[tid + 512]);
        float4 d = __ldcs(&in[tid + 768]);
        __stcs(&out[tid],       lwta4(a));
        __stcs(&out[tid + 256], lwta4(b));
        __stcs(&out[tid + 512], lwta4(c));
        __stcs(&out[tid + 768], lwta4(d));
    } else {
        #pragma unroll
        for (int k = 0; k < UNROLL; k++) {
            int i = tid + k * 256;
            if (i < n_groups) {
                __stcs(&out[i], lwta4(__ldcs(&in[i])));
            }
        }
    }
}

extern "C" void kernel_launch(void* const* d_in, const int* in_sizes, int n_in,
                              void* d_out, int out_size) {
    const float4* in = (const float4*)d_in[0];
    float4* out = (float4*)d_out;
    int n = in_sizes[0];              // 4096*8192 = 33554432 floats
    int n_groups = n / 4;             // 8388608 float4 groups
    int groups_per_block = 256 * 4;   // unroll 4
    int blocks = (n_groups + groups_per_block - 1) / groups_per_block;  // 8192
    lwta_kernel<<<blocks, 256>>>(in, out, n_groups);
}

// round 3
// speedup vs baseline: 1.2541x; 1.0172x over previous
#include <cuda_runtime.h>
#include <cstdint>

// LWTA over groups of 4 consecutive fp32 units. One float4 == one pool group.
// Keep first max (strict > matches jnp.argmax first-tie), zero rest.
// Block-strided unroll-8: every LDG.128/STG.128 fully coalesced, 8 loads
// front-batched per thread (MLP=8) to cover ~577cyc DRAM latency.

__device__ __forceinline__ float4 lwta4(float4 v) {
    float m = v.x; int idx = 0;
    if (v.y > m) { m = v.y; idx = 1; }
    if (v.z > m) { m = v.z; idx = 2; }
    if (v.w > m) { m = v.w; idx = 3; }
    float4 r;
    r.x = (idx == 0) ? v.x : 0.0f;
    r.y = (idx == 1) ? v.y : 0.0f;
    r.z = (idx == 2) ? v.z : 0.0f;
    r.w = (idx == 3) ? v.w : 0.0f;
    return r;
}

__global__ void __launch_bounds__(256) lwta_kernel(const float4* __restrict__ in,
                                                   float4* __restrict__ out,
                                                   int n_groups) {
    const int UNROLL = 8;
    int block_base = blockIdx.x * (blockDim.x * UNROLL);
    int tid = block_base + threadIdx.x;

    if (block_base + blockDim.x * UNROLL <= n_groups) {
        float4 v[UNROLL];
        #pragma unroll
        for (int k = 0; k < UNROLL; k++)
            v[k] = __ldcs(&in[tid + k * 256]);
        #pragma unroll
        for (int k = 0; k < UNROLL; k++)
            __stcs(&out[tid + k * 256], lwta4(v[k]));
    } else {
        #pragma unroll
        for (int k = 0; k < UNROLL; k++) {
            int i = tid + k * 256;
            if (i < n_groups)
                __stcs(&out[i], lwta4(__ldcs(&in[i])));
        }
    }
}

extern "C" void kernel_launch(void* const* d_in, const int* in_sizes, int n_in,
                              void* d_out, int out_size) {
    const float4* in = (const float4*)d_in[0];
    float4* out = (float4*)d_out;
    int n = in_sizes[0];              // 4096*8192 = 33554432 floats
    int n_groups = n / 4;             // 8388608 float4 groups
    int groups_per_block = 256 * 8;   // unroll 8
    int blocks = (n_groups + groups_per_block - 1) / groups_per_block;  // 4096
    lwta_kernel<<<blocks, 256>>>(in, out, n_groups);
}